// round 3
// baseline (speedup 1.0000x reference)
#include <cuda_runtime.h>
#include <math.h>

// Problem dims (fixed by the dataset)
#define NQ 1024
#define BB 8
#define MM 1024
#define CC 640
#define ROWS 8192                 // NQ*BB == BB*MM
#define LOG2E_OVER_EPS 28.853900817779268f   // log2(e)/0.05 ; note 20*log2(e) == same value
#define SCORE_SCALE 1048576.0f    // M*Nq

// ---------------- scratch (static device arrays; no allocation) ----------------
__device__ float g_q[ROWS * CC];
__device__ float g_k[ROWS * CC];
__device__ float g_v[ROWS * CC];
__device__ float g_x[ROWS * CC];
__device__ float g_sim[BB * MM * NQ];   // sim[b][m][n]
__device__ float g_E[BB * MM * NQ];     // scaled kernel exp((sim-1)/eps)*e^20 ; becomes T after finalize
__device__ float g_a[BB * MM];
__device__ float g_bv[BB * NQ];
__device__ float g_mu[BB];
__device__ int   g_mode[1];

// ---------------- mask dtype detection ----------------
// mask may arrive as uint8 (numpy bool), int32, or float32. We only know it has
// 8192 elements. The first 8KB is safe to read under every layout; classify it.
__global__ void detect_mask_kernel(const unsigned int* __restrict__ m, int* __restrict__ mode)
{
    __shared__ int ok[2]; // ok[0]: int32 {0,1}, ok[1]: float32 {0,1.0f}
    if (threadIdx.x == 0) { ok[0] = 1; ok[1] = 1; }
    __syncthreads();
    for (int i = threadIdx.x; i < 2048; i += blockDim.x) {
        unsigned v = m[i];
        if (v > 1u) ok[0] = 0;
        if (v != 0u && v != 0x3F800000u) ok[1] = 0;
    }
    __syncthreads();
    if (threadIdx.x == 0) *mode = ok[0] ? 1 : (ok[1] ? 2 : 0);
}

__device__ __forceinline__ bool mget(const void* mask, int i, int mode)
{
    if (mode == 1) return ((const int*)mask)[i] != 0;
    if (mode == 2) return ((const float*)mask)[i] != 0.0f;
    return ((const unsigned char*)mask)[i] != 0;
}

// ---------------- GEMM tiles ----------------
#define BMT 128
#define BNT 128
#define BKT 32

// C[r][c] = sum_k A[r][k]*B[c][k] + bias[c]   (X @ W^T + b pattern)
__global__ void __launch_bounds__(256, 2) gemm_nt_bias(
    const float* __restrict__ A, const float* __restrict__ B,
    const float* __restrict__ bias, float* __restrict__ C,
    int K, int lda, int ldb, int ldc)
{
    __shared__ float As[BKT][BMT];
    __shared__ float Bs[BKT][BNT];
    const int tid = threadIdx.x;
    const int tx = tid & 15, ty = tid >> 4;
    const int row0 = blockIdx.y * BMT, col0 = blockIdx.x * BNT;
    float acc[8][8] = {};
    for (int k0 = 0; k0 < K; k0 += BKT) {
#pragma unroll
        for (int j = 0; j < 4; j++) {
            int idx = tid * 4 + j;          // 0..1023 : 128 rows x 8 float4
            int r = idx >> 3, c4 = idx & 7;
            float4 v = *(const float4*)(A + (row0 + r) * lda + k0 + c4 * 4);
            As[c4 * 4 + 0][r] = v.x; As[c4 * 4 + 1][r] = v.y;
            As[c4 * 4 + 2][r] = v.z; As[c4 * 4 + 3][r] = v.w;
        }
#pragma unroll
        for (int j = 0; j < 4; j++) {
            int idx = tid * 4 + j;
            int r = idx >> 3, c4 = idx & 7;
            float4 v = *(const float4*)(B + (col0 + r) * ldb + k0 + c4 * 4);
            Bs[c4 * 4 + 0][r] = v.x; Bs[c4 * 4 + 1][r] = v.y;
            Bs[c4 * 4 + 2][r] = v.z; Bs[c4 * 4 + 3][r] = v.w;
        }
        __syncthreads();
#pragma unroll
        for (int kk = 0; kk < BKT; kk++) {
            float a[8], b[8];
            *(float4*)a       = *(const float4*)&As[kk][ty * 8];
            *(float4*)(a + 4) = *(const float4*)&As[kk][ty * 8 + 4];
            *(float4*)b       = *(const float4*)&Bs[kk][tx * 8];
            *(float4*)(b + 4) = *(const float4*)&Bs[kk][tx * 8 + 4];
#pragma unroll
            for (int i = 0; i < 8; i++)
#pragma unroll
                for (int jj = 0; jj < 8; jj++)
                    acc[i][jj] = fmaf(a[i], b[jj], acc[i][jj]);
        }
        __syncthreads();
    }
    float bvals[8];
    *(float4*)bvals       = *(const float4*)(bias + col0 + tx * 8);
    *(float4*)(bvals + 4) = *(const float4*)(bias + col0 + tx * 8 + 4);
#pragma unroll
    for (int i = 0; i < 8; i++) {
        float* cr = C + (row0 + ty * 8 + i) * ldc + col0 + tx * 8;
        float4 o0, o1;
        o0.x = acc[i][0] + bvals[0]; o0.y = acc[i][1] + bvals[1];
        o0.z = acc[i][2] + bvals[2]; o0.w = acc[i][3] + bvals[3];
        o1.x = acc[i][4] + bvals[4]; o1.y = acc[i][5] + bvals[5];
        o1.z = acc[i][6] + bvals[6]; o1.w = acc[i][7] + bvals[7];
        *(float4*)cr = o0; *(float4*)(cr + 4) = o1;
    }
}

// sim[b][m][n] = k_hat[b,m,:] . q_hat[n,b,:] ; also E = exp((sim-1)/eps)*e^20 (0 for masked-out m)
__global__ void __launch_bounds__(256, 2) gemm_sim(
    const float* __restrict__ Kn, const float* __restrict__ Qn,
    const void* __restrict__ mask, const int* __restrict__ mode,
    float* __restrict__ sim, float* __restrict__ E)
{
    __shared__ float As[BKT][BMT];
    __shared__ float Bs[BKT][BNT];
    const int tid = threadIdx.x;
    const int tx = tid & 15, ty = tid >> 4;
    const int b = blockIdx.z;
    const int row0 = blockIdx.y * BMT, col0 = blockIdx.x * BNT;  // row=m, col=n
    const float* A = Kn + b * MM * CC;
    float acc[8][8] = {};
    for (int k0 = 0; k0 < CC; k0 += BKT) {
#pragma unroll
        for (int j = 0; j < 4; j++) {
            int idx = tid * 4 + j;
            int r = idx >> 3, c4 = idx & 7;
            float4 v = *(const float4*)(A + (row0 + r) * CC + k0 + c4 * 4);
            As[c4 * 4 + 0][r] = v.x; As[c4 * 4 + 1][r] = v.y;
            As[c4 * 4 + 2][r] = v.z; As[c4 * 4 + 3][r] = v.w;
        }
#pragma unroll
        for (int j = 0; j < 4; j++) {
            int idx = tid * 4 + j;
            int r = idx >> 3, c4 = idx & 7;
            // q row for logical n = col0+r lives at ((n)*BB + b)
            float4 v = *(const float4*)(Qn + ((col0 + r) * BB + b) * CC + k0 + c4 * 4);
            Bs[c4 * 4 + 0][r] = v.x; Bs[c4 * 4 + 1][r] = v.y;
            Bs[c4 * 4 + 2][r] = v.z; Bs[c4 * 4 + 3][r] = v.w;
        }
        __syncthreads();
#pragma unroll
        for (int kk = 0; kk < BKT; kk++) {
            float a[8], bb[8];
            *(float4*)a        = *(const float4*)&As[kk][ty * 8];
            *(float4*)(a + 4)  = *(const float4*)&As[kk][ty * 8 + 4];
            *(float4*)bb       = *(const float4*)&Bs[kk][tx * 8];
            *(float4*)(bb + 4) = *(const float4*)&Bs[kk][tx * 8 + 4];
#pragma unroll
            for (int i = 0; i < 8; i++)
#pragma unroll
                for (int jj = 0; jj < 8; jj++)
                    acc[i][jj] = fmaf(a[i], bb[jj], acc[i][jj]);
        }
        __syncthreads();
    }
    const int md = *mode;
#pragma unroll
    for (int i = 0; i < 8; i++) {
        int m = row0 + ty * 8 + i;
        bool act = mget(mask, (b << 10) + m, md);
        int base = (b << 20) + (m << 10) + col0 + tx * 8;
#pragma unroll
        for (int jj = 0; jj < 8; jj++) {
            float s = acc[i][jj];
            sim[base + jj] = s;
            E[base + jj] = act ? exp2f(LOG2E_OVER_EPS * s) : 0.0f;
        }
    }
}

// x[n][c] = sum_m T[b][m][n] * v[b][m][c]   (A accessed K-major: no transpose needed)
__global__ void __launch_bounds__(256, 2) gemm_tn_x(
    const float* __restrict__ T, const float* __restrict__ V, float* __restrict__ X)
{
    __shared__ float As[BKT][BMT];  // [m][n]
    __shared__ float Bs[BKT][BNT];  // [m][c]
    const int tid = threadIdx.x;
    const int tx = tid & 15, ty = tid >> 4;
    const int b = blockIdx.z;
    const int n0 = blockIdx.y * BMT, c0 = blockIdx.x * BNT;
    const float* Tb = T + (b << 20);
    const float* Vb = V + b * MM * CC;
    float acc[8][8] = {};
    for (int m0 = 0; m0 < MM; m0 += BKT) {
#pragma unroll
        for (int j = 0; j < 4; j++) {
            int idx = tid * 4 + j;          // 32 rows x 32 float4
            int mr = idx >> 5, c4 = idx & 31;
            *(float4*)&As[mr][c4 * 4] = *(const float4*)(Tb + (m0 + mr) * NQ + n0 + c4 * 4);
        }
#pragma unroll
        for (int j = 0; j < 4; j++) {
            int idx = tid * 4 + j;
            int mr = idx >> 5, c4 = idx & 31;
            *(float4*)&Bs[mr][c4 * 4] = *(const float4*)(Vb + (m0 + mr) * CC + c0 + c4 * 4);
        }
        __syncthreads();
#pragma unroll
        for (int kk = 0; kk < BKT; kk++) {
            float a[8], bb[8];
            *(float4*)a        = *(const float4*)&As[kk][ty * 8];
            *(float4*)(a + 4)  = *(const float4*)&As[kk][ty * 8 + 4];
            *(float4*)bb       = *(const float4*)&Bs[kk][tx * 8];
            *(float4*)(bb + 4) = *(const float4*)&Bs[kk][tx * 8 + 4];
#pragma unroll
            for (int i = 0; i < 8; i++)
#pragma unroll
                for (int jj = 0; jj < 8; jj++)
                    acc[i][jj] = fmaf(a[i], bb[jj], acc[i][jj]);
        }
        __syncthreads();
    }
#pragma unroll
    for (int i = 0; i < 8; i++) {
        int n = n0 + ty * 8 + i;
        float* xr = X + (n * BB + b) * CC + c0 + tx * 8;
        float4 o0, o1;
        o0.x = acc[i][0]; o0.y = acc[i][1]; o0.z = acc[i][2]; o0.w = acc[i][3];
        o1.x = acc[i][4]; o1.y = acc[i][5]; o1.z = acc[i][6]; o1.w = acc[i][7];
        *(float4*)xr = o0; *(float4*)(xr + 4) = o1;
    }
}

// ---------------- small kernels ----------------
__global__ void __launch_bounds__(128) l2norm_rows(float* __restrict__ X)
{
    const int r = blockIdx.x;
    float* row = X + r * CC;
    float ss = 0.0f;
#pragma unroll
    for (int i = 0; i < 5; i++) { float v = row[threadIdx.x + i * 128]; ss = fmaf(v, v, ss); }
    for (int o = 16; o; o >>= 1) ss += __shfl_down_sync(0xffffffffu, ss, o);
    __shared__ float ws[4];
    if ((threadIdx.x & 31) == 0) ws[threadIdx.x >> 5] = ss;
    __syncthreads();
    float tot = ws[0] + ws[1] + ws[2] + ws[3];
    float inv = 1.0f / fmaxf(sqrtf(tot), 1e-12f);
#pragma unroll
    for (int i = 0; i < 5; i++) row[threadIdx.x + i * 128] *= inv;
}

__global__ void __launch_bounds__(256) init_mu_b(
    const void* __restrict__ mask, const int* __restrict__ mode,
    float* __restrict__ mu, float* __restrict__ bvec)
{
    const int b = blockIdx.x;
    const int md = *mode;
    int cnt = 0;
    for (int i = threadIdx.x; i < MM; i += 256) cnt += mget(mask, b * MM + i, md) ? 1 : 0;
    for (int o = 16; o; o >>= 1) cnt += __shfl_down_sync(0xffffffffu, cnt, o);
    __shared__ int ws[8];
    if ((threadIdx.x & 31) == 0) ws[threadIdx.x >> 5] = cnt;
    __syncthreads();
    if (threadIdx.x == 0) {
        int c = 0;
        for (int i = 0; i < 8; i++) c += ws[i];
        int cm = c > 1 ? c : 1;
        mu[b] = 1.0f / (float)cm + 1e-8f;
    }
    for (int i = threadIdx.x; i < NQ; i += 256) bvec[b * NQ + i] = 1.0f;
}

// a[b][m] = mu_eff[b] / sum_n E[b][m][n]*bvec[b][n]     (one warp per row)
__global__ void __launch_bounds__(256) sk_row(
    const float* __restrict__ E, const float* __restrict__ bv,
    const float* __restrict__ mu, const void* __restrict__ mask,
    const int* __restrict__ mode, float* __restrict__ a)
{
    const int w = threadIdx.x >> 5, lane = threadIdx.x & 31;
    const int r = blockIdx.x * 8 + w;
    const int b = r >> 10;
    if (!mget(mask, r, *mode)) { if (lane == 0) a[r] = 0.0f; return; }
    const float4* Er = (const float4*)(E + ((size_t)b << 20) + (size_t)(r & 1023) * NQ);
    const float4* Bv = (const float4*)(bv + (b << 10));
    float s = 0.0f;
#pragma unroll
    for (int t = 0; t < 8; t++) {
        float4 e = Er[t * 32 + lane];
        float4 bb = Bv[t * 32 + lane];
        s = fmaf(e.x, bb.x, s); s = fmaf(e.y, bb.y, s);
        s = fmaf(e.z, bb.z, s); s = fmaf(e.w, bb.w, s);
    }
    for (int o = 16; o; o >>= 1) s += __shfl_down_sync(0xffffffffu, s, o);
    if (lane == 0) a[r] = (s > 0.0f) ? mu[b] / s : 0.0f;
}

// bvec[b][n] = nu_eff / sum_m E[b][m][n]*a[b][m]   (block per (b, 64-col chunk))
__global__ void __launch_bounds__(256) sk_col(
    const float* __restrict__ E, const float* __restrict__ a,
    float* __restrict__ bv, float nu_eff)
{
    __shared__ float part[8][64];
    const int b = blockIdx.y;
    const int n0 = blockIdx.x * 64;
    const int w = threadIdx.x >> 5, lane = threadIdx.x & 31;
    const int n = n0 + lane * 2;
    const float* Eb = E + ((size_t)b << 20);
    const float* ab = a + (b << 10);
    float accx = 0.0f, accy = 0.0f;
#pragma unroll 4
    for (int m = w; m < MM; m += 8) {
        float am = ab[m];
        if (am != 0.0f) {
            float2 e = *(const float2*)(Eb + (size_t)m * NQ + n);
            accx = fmaf(am, e.x, accx);
            accy = fmaf(am, e.y, accy);
        }
    }
    part[w][lane * 2] = accx;
    part[w][lane * 2 + 1] = accy;
    __syncthreads();
    if (threadIdx.x < 64) {
        float c = 0.0f;
#pragma unroll
        for (int ww = 0; ww < 8; ww++) c += part[ww][threadIdx.x];
        bv[(b << 10) + n0 + threadIdx.x] = (c > 0.0f) ? nu_eff / c : 0.0f;
    }
}

// E <- T = a[m]*E*bvec[n]
__global__ void __launch_bounds__(256) finalize_T(
    float* __restrict__ E, const float* __restrict__ a, const float* __restrict__ bv)
{
    const int r = blockIdx.x;            // b*1024+m
    const int b = r >> 10;
    const float am = a[r];
    float4* Er = (float4*)(E + ((size_t)b << 20) + (size_t)(r & 1023) * NQ);
    if (am == 0.0f) return;              // row already all-zero
    const float4* Bv = (const float4*)(bv + (b << 10));
    const int i = threadIdx.x;           // 256 float4 per row, 256 threads
    float4 e = Er[i];
    float4 bb = Bv[i];
    e.x *= am * bb.x; e.y *= am * bb.y; e.z *= am * bb.z; e.w *= am * bb.w;
    Er[i] = e;
}

// attn_save[b][m] = mask ? M*Nq * sum_n sim*T : 0
__global__ void __launch_bounds__(256) attn_row(
    const float* __restrict__ sim, const float* __restrict__ T,
    const void* __restrict__ mask, const int* __restrict__ mode,
    float* __restrict__ outA)
{
    const int w = threadIdx.x >> 5, lane = threadIdx.x & 31;
    const int r = blockIdx.x * 8 + w;
    const int b = r >> 10;
    if (!mget(mask, r, *mode)) { if (lane == 0) outA[r] = 0.0f; return; }
    size_t base = ((size_t)b << 20) + (size_t)(r & 1023) * NQ;
    const float4* Sr = (const float4*)(sim + base);
    const float4* Tr = (const float4*)(T + base);
    float s = 0.0f;
#pragma unroll
    for (int t = 0; t < 8; t++) {
        float4 sv = Sr[t * 32 + lane];
        float4 tv = Tr[t * 32 + lane];
        s = fmaf(sv.x, tv.x, s); s = fmaf(sv.y, tv.y, s);
        s = fmaf(sv.z, tv.z, s); s = fmaf(sv.w, tv.w, s);
    }
    for (int o = 16; o; o >>= 1) s += __shfl_down_sync(0xffffffffu, s, o);
    if (lane == 0) outA[r] = SCORE_SCALE * s;
}

// ---------------- launch ----------------
extern "C" void kernel_launch(void* const* d_in, const int* in_sizes, int n_in,
                              void* d_out, int out_size)
{
    const float* xq = (const float*)d_in[0];
    const float* xk = (const float*)d_in[1];
    const float* xv = (const float*)d_in[2];
    const void*  mask = d_in[3];
    const float* Wq = (const float*)d_in[4];
    const float* bq = (const float*)d_in[5];
    const float* Wk = (const float*)d_in[6];
    const float* bk = (const float*)d_in[7];
    const float* Wv = (const float*)d_in[8];
    const float* bv_in = (const float*)d_in[9];
    const float* Wp = (const float*)d_in[10];
    const float* bp = (const float*)d_in[11];
    float* out = (float*)d_out;

    float *p_q, *p_k, *p_v, *p_x, *p_sim, *p_E, *p_a, *p_bv, *p_mu;
    int* p_mode;
    cudaGetSymbolAddress((void**)&p_q, g_q);
    cudaGetSymbolAddress((void**)&p_k, g_k);
    cudaGetSymbolAddress((void**)&p_v, g_v);
    cudaGetSymbolAddress((void**)&p_x, g_x);
    cudaGetSymbolAddress((void**)&p_sim, g_sim);
    cudaGetSymbolAddress((void**)&p_E, g_E);
    cudaGetSymbolAddress((void**)&p_a, g_a);
    cudaGetSymbolAddress((void**)&p_bv, g_bv);
    cudaGetSymbolAddress((void**)&p_mu, g_mu);
    cudaGetSymbolAddress((void**)&p_mode, g_mode);

    detect_mask_kernel<<<1, 256>>>((const unsigned int*)mask, p_mode);

    dim3 gproj(CC / BNT, ROWS / BMT);   // (5, 64)
    gemm_nt_bias<<<gproj, 256>>>(xq, Wq, bq, p_q, CC, CC, CC, CC);
    gemm_nt_bias<<<gproj, 256>>>(xk, Wk, bk, p_k, CC, CC, CC, CC);
    gemm_nt_bias<<<gproj, 256>>>(xv, Wv, bv_in, p_v, CC, CC, CC, CC);

    l2norm_rows<<<ROWS, 128>>>(p_q);
    l2norm_rows<<<ROWS, 128>>>(p_k);

    init_mu_b<<<BB, 256>>>(mask, p_mode, p_mu, p_bv);

    dim3 gsim(NQ / BNT, MM / BMT, BB);  // (8, 8, 8)
    gemm_sim<<<gsim, 256>>>(p_k, p_q, mask, p_mode, p_sim, p_E);

    const float nu_eff = 1.0f / (float)NQ + 1e-8f;
    for (int it = 0; it < 100; it++) {
        sk_row<<<ROWS / 8, 256>>>(p_E, p_bv, p_mu, mask, p_mode, p_a);
        sk_col<<<dim3(NQ / 64, BB), 256>>>(p_E, p_a, p_bv, nu_eff);
    }

    finalize_T<<<ROWS, 256>>>(p_E, p_a, p_bv);

    if (out_size >= NQ * BB * CC + BB * MM) {
        attn_row<<<ROWS / 8, 256>>>(p_sim, p_E, mask, p_mode, out + NQ * BB * CC);
    }

    dim3 gx(CC / BNT, NQ / BMT, BB);    // (5, 8, 8)
    gemm_tn_x<<<gx, 256>>>(p_E, p_v, p_x);

    gemm_nt_bias<<<gproj, 256>>>(p_x, Wp, bp, out, CC, CC, CC, CC);
}

// round 4
// speedup vs baseline: 1.5664x; 1.5664x over previous
#include <cuda_runtime.h>
#include <math.h>

// Problem dims (fixed by the dataset)
#define NQ 1024
#define BB 8
#define MM 1024
#define CC 640
#define ROWS 8192                 // NQ*BB == BB*MM
#define LOG2E_OVER_EPS 28.853900817779268f   // log2(e)/0.05 ; note 20*log2(e) == same value
#define SCORE_SCALE 1048576.0f    // M*Nq
#define SK_CHUNKS 32              // row-chunks per batch in fused sinkhorn kernel

// ---------------- scratch (static device arrays; no allocation) ----------------
__device__ float g_q[ROWS * CC];
__device__ float g_k[ROWS * CC];
__device__ float g_v[ROWS * CC];
__device__ float g_x[ROWS * CC];
__device__ float g_sim[BB * MM * NQ];   // sim[b][m][n]
__device__ float g_E[BB * MM * NQ];     // scaled kernel exp((sim-1)/eps)*e^20 ; becomes T after finalize
__device__ float g_a[BB * MM];
__device__ float g_bv[BB * NQ];
__device__ float g_part[BB * SK_CHUNKS * NQ];
__device__ float g_mu[BB];
__device__ int   g_mode[1];

// ---------------- mask dtype detection ----------------
__global__ void detect_mask_kernel(const unsigned int* __restrict__ m, int* __restrict__ mode)
{
    __shared__ int ok[2]; // ok[0]: int32 {0,1}, ok[1]: float32 {0,1.0f}
    if (threadIdx.x == 0) { ok[0] = 1; ok[1] = 1; }
    __syncthreads();
    for (int i = threadIdx.x; i < 2048; i += blockDim.x) {
        unsigned v = m[i];
        if (v > 1u) ok[0] = 0;
        if (v != 0u && v != 0x3F800000u) ok[1] = 0;
    }
    __syncthreads();
    if (threadIdx.x == 0) *mode = ok[0] ? 1 : (ok[1] ? 2 : 0);
}

__device__ __forceinline__ bool mget(const void* mask, int i, int mode)
{
    if (mode == 1) return ((const int*)mask)[i] != 0;
    if (mode == 2) return ((const float*)mask)[i] != 0.0f;
    return ((const unsigned char*)mask)[i] != 0;
}

// ---------------- GEMM tiles ----------------
#define BMT 128
#define BNT 128
#define BKT 32

// C[r][c] = sum_k A[r][k]*B[c][k] + bias[c]   (X @ W^T + b pattern)
__global__ void __launch_bounds__(256, 2) gemm_nt_bias(
    const float* __restrict__ A, const float* __restrict__ B,
    const float* __restrict__ bias, float* __restrict__ C,
    int K, int lda, int ldb, int ldc)
{
    __shared__ float As[BKT][BMT];
    __shared__ float Bs[BKT][BNT];
    const int tid = threadIdx.x;
    const int tx = tid & 15, ty = tid >> 4;
    const int row0 = blockIdx.y * BMT, col0 = blockIdx.x * BNT;
    float acc[8][8] = {};
    for (int k0 = 0; k0 < K; k0 += BKT) {
#pragma unroll
        for (int j = 0; j < 4; j++) {
            int idx = tid * 4 + j;          // 0..1023 : 128 rows x 8 float4
            int r = idx >> 3, c4 = idx & 7;
            float4 v = *(const float4*)(A + (row0 + r) * lda + k0 + c4 * 4);
            As[c4 * 4 + 0][r] = v.x; As[c4 * 4 + 1][r] = v.y;
            As[c4 * 4 + 2][r] = v.z; As[c4 * 4 + 3][r] = v.w;
        }
#pragma unroll
        for (int j = 0; j < 4; j++) {
            int idx = tid * 4 + j;
            int r = idx >> 3, c4 = idx & 7;
            float4 v = *(const float4*)(B + (col0 + r) * ldb + k0 + c4 * 4);
            Bs[c4 * 4 + 0][r] = v.x; Bs[c4 * 4 + 1][r] = v.y;
            Bs[c4 * 4 + 2][r] = v.z; Bs[c4 * 4 + 3][r] = v.w;
        }
        __syncthreads();
#pragma unroll
        for (int kk = 0; kk < BKT; kk++) {
            float a[8], b[8];
            *(float4*)a       = *(const float4*)&As[kk][ty * 8];
            *(float4*)(a + 4) = *(const float4*)&As[kk][ty * 8 + 4];
            *(float4*)b       = *(const float4*)&Bs[kk][tx * 8];
            *(float4*)(b + 4) = *(const float4*)&Bs[kk][tx * 8 + 4];
#pragma unroll
            for (int i = 0; i < 8; i++)
#pragma unroll
                for (int jj = 0; jj < 8; jj++)
                    acc[i][jj] = fmaf(a[i], b[jj], acc[i][jj]);
        }
        __syncthreads();
    }
    float bvals[8];
    *(float4*)bvals       = *(const float4*)(bias + col0 + tx * 8);
    *(float4*)(bvals + 4) = *(const float4*)(bias + col0 + tx * 8 + 4);
#pragma unroll
    for (int i = 0; i < 8; i++) {
        float* cr = C + (row0 + ty * 8 + i) * ldc + col0 + tx * 8;
        float4 o0, o1;
        o0.x = acc[i][0] + bvals[0]; o0.y = acc[i][1] + bvals[1];
        o0.z = acc[i][2] + bvals[2]; o0.w = acc[i][3] + bvals[3];
        o1.x = acc[i][4] + bvals[4]; o1.y = acc[i][5] + bvals[5];
        o1.z = acc[i][6] + bvals[6]; o1.w = acc[i][7] + bvals[7];
        *(float4*)cr = o0; *(float4*)(cr + 4) = o1;
    }
}

// sim[b][m][n] = k_hat[b,m,:] . q_hat[n,b,:] ; also E = exp((sim-1)/eps)*e^20 (0 for masked-out m)
__global__ void __launch_bounds__(256, 2) gemm_sim(
    const float* __restrict__ Kn, const float* __restrict__ Qn,
    const void* __restrict__ mask, const int* __restrict__ mode,
    float* __restrict__ sim, float* __restrict__ E)
{
    __shared__ float As[BKT][BMT];
    __shared__ float Bs[BKT][BNT];
    const int tid = threadIdx.x;
    const int tx = tid & 15, ty = tid >> 4;
    const int b = blockIdx.z;
    const int row0 = blockIdx.y * BMT, col0 = blockIdx.x * BNT;  // row=m, col=n
    const float* A = Kn + b * MM * CC;
    float acc[8][8] = {};
    for (int k0 = 0; k0 < CC; k0 += BKT) {
#pragma unroll
        for (int j = 0; j < 4; j++) {
            int idx = tid * 4 + j;
            int r = idx >> 3, c4 = idx & 7;
            float4 v = *(const float4*)(A + (row0 + r) * CC + k0 + c4 * 4);
            As[c4 * 4 + 0][r] = v.x; As[c4 * 4 + 1][r] = v.y;
            As[c4 * 4 + 2][r] = v.z; As[c4 * 4 + 3][r] = v.w;
        }
#pragma unroll
        for (int j = 0; j < 4; j++) {
            int idx = tid * 4 + j;
            int r = idx >> 3, c4 = idx & 7;
            float4 v = *(const float4*)(Qn + ((col0 + r) * BB + b) * CC + k0 + c4 * 4);
            Bs[c4 * 4 + 0][r] = v.x; Bs[c4 * 4 + 1][r] = v.y;
            Bs[c4 * 4 + 2][r] = v.z; Bs[c4 * 4 + 3][r] = v.w;
        }
        __syncthreads();
#pragma unroll
        for (int kk = 0; kk < BKT; kk++) {
            float a[8], bb[8];
            *(float4*)a        = *(const float4*)&As[kk][ty * 8];
            *(float4*)(a + 4)  = *(const float4*)&As[kk][ty * 8 + 4];
            *(float4*)bb       = *(const float4*)&Bs[kk][tx * 8];
            *(float4*)(bb + 4) = *(const float4*)&Bs[kk][tx * 8 + 4];
#pragma unroll
            for (int i = 0; i < 8; i++)
#pragma unroll
                for (int jj = 0; jj < 8; jj++)
                    acc[i][jj] = fmaf(a[i], bb[jj], acc[i][jj]);
        }
        __syncthreads();
    }
    const int md = *mode;
#pragma unroll
    for (int i = 0; i < 8; i++) {
        int m = row0 + ty * 8 + i;
        bool act = mget(mask, (b << 10) + m, md);
        int base = (b << 20) + (m << 10) + col0 + tx * 8;
#pragma unroll
        for (int jj = 0; jj < 8; jj++) {
            float s = acc[i][jj];
            sim[base + jj] = s;
            E[base + jj] = act ? exp2f(LOG2E_OVER_EPS * s) : 0.0f;
        }
    }
}

// x[n][c] = sum_m T[b][m][n] * v[b][m][c]
__global__ void __launch_bounds__(256, 2) gemm_tn_x(
    const float* __restrict__ T, const float* __restrict__ V, float* __restrict__ X)
{
    __shared__ float As[BKT][BMT];  // [m][n]
    __shared__ float Bs[BKT][BNT];  // [m][c]
    const int tid = threadIdx.x;
    const int tx = tid & 15, ty = tid >> 4;
    const int b = blockIdx.z;
    const int n0 = blockIdx.y * BMT, c0 = blockIdx.x * BNT;
    const float* Tb = T + (b << 20);
    const float* Vb = V + b * MM * CC;
    float acc[8][8] = {};
    for (int m0 = 0; m0 < MM; m0 += BKT) {
#pragma unroll
        for (int j = 0; j < 4; j++) {
            int idx = tid * 4 + j;          // 32 rows x 32 float4
            int mr = idx >> 5, c4 = idx & 31;
            *(float4*)&As[mr][c4 * 4] = *(const float4*)(Tb + (m0 + mr) * NQ + n0 + c4 * 4);
        }
#pragma unroll
        for (int j = 0; j < 4; j++) {
            int idx = tid * 4 + j;
            int mr = idx >> 5, c4 = idx & 31;
            *(float4*)&Bs[mr][c4 * 4] = *(const float4*)(Vb + (m0 + mr) * CC + c0 + c4 * 4);
        }
        __syncthreads();
#pragma unroll
        for (int kk = 0; kk < BKT; kk++) {
            float a[8], bb[8];
            *(float4*)a        = *(const float4*)&As[kk][ty * 8];
            *(float4*)(a + 4)  = *(const float4*)&As[kk][ty * 8 + 4];
            *(float4*)bb       = *(const float4*)&Bs[kk][tx * 8];
            *(float4*)(bb + 4) = *(const float4*)&Bs[kk][tx * 8 + 4];
#pragma unroll
            for (int i = 0; i < 8; i++)
#pragma unroll
                for (int jj = 0; jj < 8; jj++)
                    acc[i][jj] = fmaf(a[i], bb[jj], acc[i][jj]);
        }
        __syncthreads();
    }
#pragma unroll
    for (int i = 0; i < 8; i++) {
        int n = n0 + ty * 8 + i;
        float* xr = X + (n * BB + b) * CC + c0 + tx * 8;
        float4 o0, o1;
        o0.x = acc[i][0]; o0.y = acc[i][1]; o0.z = acc[i][2]; o0.w = acc[i][3];
        o1.x = acc[i][4]; o1.y = acc[i][5]; o1.z = acc[i][6]; o1.w = acc[i][7];
        *(float4*)xr = o0; *(float4*)(xr + 4) = o1;
    }
}

// ---------------- small kernels ----------------
__global__ void __launch_bounds__(128) l2norm_rows(float* __restrict__ X)
{
    const int r = blockIdx.x;
    float* row = X + r * CC;
    float ss = 0.0f;
#pragma unroll
    for (int i = 0; i < 5; i++) { float v = row[threadIdx.x + i * 128]; ss = fmaf(v, v, ss); }
    for (int o = 16; o; o >>= 1) ss += __shfl_down_sync(0xffffffffu, ss, o);
    __shared__ float ws[4];
    if ((threadIdx.x & 31) == 0) ws[threadIdx.x >> 5] = ss;
    __syncthreads();
    float tot = ws[0] + ws[1] + ws[2] + ws[3];
    float inv = 1.0f / fmaxf(sqrtf(tot), 1e-12f);
#pragma unroll
    for (int i = 0; i < 5; i++) row[threadIdx.x + i * 128] *= inv;
}

__global__ void __launch_bounds__(256) init_mu_b(
    const void* __restrict__ mask, const int* __restrict__ mode,
    float* __restrict__ mu, float* __restrict__ bvec)
{
    const int b = blockIdx.x;
    const int md = *mode;
    int cnt = 0;
    for (int i = threadIdx.x; i < MM; i += 256) cnt += mget(mask, b * MM + i, md) ? 1 : 0;
    for (int o = 16; o; o >>= 1) cnt += __shfl_down_sync(0xffffffffu, cnt, o);
    __shared__ int ws[8];
    if ((threadIdx.x & 31) == 0) ws[threadIdx.x >> 5] = cnt;
    __syncthreads();
    if (threadIdx.x == 0) {
        int c = 0;
        for (int i = 0; i < 8; i++) c += ws[i];
        int cm = c > 1 ? c : 1;
        mu[b] = 1.0f / (float)cm + 1e-8f;
    }
    for (int i = threadIdx.x; i < NQ; i += 256) bvec[b * NQ + i] = 1.0f;
}

// ---------------- fused Sinkhorn iteration ----------------
// One read of E per iteration. grid (SK_CHUNKS, BB), 256 threads (8 warps),
// each warp owns 4 rows (row held entirely in registers: 8 float4/lane).
// Computes a[r] = mu / sum_n E[r][n]*b[n], then accumulates a[r]*E[r][n]
// into per-block column partials; block reduces 8 warps -> partial[b][chunk][n].
__global__ void __launch_bounds__(256) sk_fused(
    const float* __restrict__ E, const float* __restrict__ bv,
    const float* __restrict__ mu, const void* __restrict__ mask,
    const int* __restrict__ mode, float* __restrict__ a,
    float* __restrict__ partial)
{
    __shared__ float sred[8][1024];
    const int b = blockIdx.y;
    const int chunk = blockIdx.x;
    const int w = threadIdx.x >> 5, lane = threadIdx.x & 31;
    const int md = *mode;
    const float mub = mu[b];
    const float4* Bv = (const float4*)(bv + (b << 10));
    float4 breg[8];
#pragma unroll
    for (int t = 0; t < 8; t++) breg[t] = Bv[t * 32 + lane];
    float4 cacc[8] = {};
    const int row0 = chunk * 32 + w * 4;
#pragma unroll
    for (int i = 0; i < 4; i++) {
        const int r = row0 + i;
        const int gr = (b << 10) + r;
        bool act = mget(mask, gr, md);          // warp-uniform
        if (!act) { if (lane == 0) a[gr] = 0.0f; continue; }
        const float4* Er = (const float4*)(E + ((size_t)b << 20) + ((size_t)r << 10));
        float4 e[8];
        float s = 0.0f;
#pragma unroll
        for (int t = 0; t < 8; t++) {
            e[t] = Er[t * 32 + lane];
            s = fmaf(e[t].x, breg[t].x, s); s = fmaf(e[t].y, breg[t].y, s);
            s = fmaf(e[t].z, breg[t].z, s); s = fmaf(e[t].w, breg[t].w, s);
        }
#pragma unroll
        for (int o = 16; o; o >>= 1) s += __shfl_xor_sync(0xffffffffu, s, o);
        float av = (s > 0.0f) ? mub / s : 0.0f;
        if (lane == 0) a[gr] = av;
#pragma unroll
        for (int t = 0; t < 8; t++) {
            cacc[t].x = fmaf(av, e[t].x, cacc[t].x);
            cacc[t].y = fmaf(av, e[t].y, cacc[t].y);
            cacc[t].z = fmaf(av, e[t].z, cacc[t].z);
            cacc[t].w = fmaf(av, e[t].w, cacc[t].w);
        }
    }
#pragma unroll
    for (int t = 0; t < 8; t++)
        *(float4*)&sred[w][t * 128 + lane * 4] = cacc[t];
    __syncthreads();
    {
        const int n = threadIdx.x * 4;
        float4 ssum = *(const float4*)&sred[0][n];
#pragma unroll
        for (int ww = 1; ww < 8; ww++) {
            float4 v = *(const float4*)&sred[ww][n];
            ssum.x += v.x; ssum.y += v.y; ssum.z += v.z; ssum.w += v.w;
        }
        *(float4*)&partial[(((b * SK_CHUNKS + chunk)) << 10) + n] = ssum;
    }
}

// bv[b][n] = nu_eff / sum_chunk partial[b][chunk][n]
__global__ void __launch_bounds__(256) sk_breduce(
    const float* __restrict__ partial, float* __restrict__ bv, float nu_eff)
{
    const int idx = blockIdx.x * 256 + threadIdx.x;   // b*1024 + n
    const int b = idx >> 10, n = idx & 1023;
    const float* p = partial + ((size_t)(b * SK_CHUNKS) << 10) + n;
    float c = 0.0f;
#pragma unroll
    for (int ch = 0; ch < SK_CHUNKS; ch++) c += p[(size_t)ch << 10];
    bv[idx] = (c > 0.0f) ? nu_eff / c : 0.0f;
}

// Fused: E <- T = a[m]*E*bvec[n], and attn[b][m] = SCORE_SCALE * sum_n sim*T (0 if masked)
__global__ void __launch_bounds__(256) finalize_T_attn(
    float* __restrict__ E, const float* __restrict__ sim,
    const float* __restrict__ a, const float* __restrict__ bv,
    float* __restrict__ outA)
{
    const int r = blockIdx.x;            // b*1024+m
    const int b = r >> 10;
    const float am = a[r];
    if (am == 0.0f) { if (threadIdx.x == 0) outA[r] = 0.0f; return; }
    const size_t base = ((size_t)b << 20) + ((size_t)(r & 1023) << 10);
    float4* Er = (float4*)(E + base);
    const float4* Sr = (const float4*)(sim + base);
    const float4* Bv = (const float4*)(bv + (b << 10));
    const int i = threadIdx.x;           // 256 float4 per row, 256 threads
    float4 e = Er[i];
    float4 bb = Bv[i];
    float4 sv = Sr[i];
    e.x *= am * bb.x; e.y *= am * bb.y; e.z *= am * bb.z; e.w *= am * bb.w;
    Er[i] = e;
    float s = sv.x * e.x + sv.y * e.y + sv.z * e.z + sv.w * e.w;
#pragma unroll
    for (int o = 16; o; o >>= 1) s += __shfl_xor_sync(0xffffffffu, s, o);
    __shared__ float ws[8];
    if ((threadIdx.x & 31) == 0) ws[threadIdx.x >> 5] = s;
    __syncthreads();
    if (threadIdx.x == 0) {
        float tot = 0.0f;
#pragma unroll
        for (int ww = 0; ww < 8; ww++) tot += ws[ww];
        outA[r] = SCORE_SCALE * tot;
    }
}

// ---------------- launch ----------------
extern "C" void kernel_launch(void* const* d_in, const int* in_sizes, int n_in,
                              void* d_out, int out_size)
{
    const float* xq = (const float*)d_in[0];
    const float* xk = (const float*)d_in[1];
    const float* xv = (const float*)d_in[2];
    const void*  mask = d_in[3];
    const float* Wq = (const float*)d_in[4];
    const float* bq = (const float*)d_in[5];
    const float* Wk = (const float*)d_in[6];
    const float* bk = (const float*)d_in[7];
    const float* Wv = (const float*)d_in[8];
    const float* bv_in = (const float*)d_in[9];
    const float* Wp = (const float*)d_in[10];
    const float* bp = (const float*)d_in[11];
    float* out = (float*)d_out;

    float *p_q, *p_k, *p_v, *p_x, *p_sim, *p_E, *p_a, *p_bv, *p_part, *p_mu;
    int* p_mode;
    cudaGetSymbolAddress((void**)&p_q, g_q);
    cudaGetSymbolAddress((void**)&p_k, g_k);
    cudaGetSymbolAddress((void**)&p_v, g_v);
    cudaGetSymbolAddress((void**)&p_x, g_x);
    cudaGetSymbolAddress((void**)&p_sim, g_sim);
    cudaGetSymbolAddress((void**)&p_E, g_E);
    cudaGetSymbolAddress((void**)&p_a, g_a);
    cudaGetSymbolAddress((void**)&p_bv, g_bv);
    cudaGetSymbolAddress((void**)&p_part, g_part);
    cudaGetSymbolAddress((void**)&p_mu, g_mu);
    cudaGetSymbolAddress((void**)&p_mode, g_mode);

    detect_mask_kernel<<<1, 256>>>((const unsigned int*)mask, p_mode);

    dim3 gproj(CC / BNT, ROWS / BMT);   // (5, 64)
    gemm_nt_bias<<<gproj, 256>>>(xq, Wq, bq, p_q, CC, CC, CC, CC);
    gemm_nt_bias<<<gproj, 256>>>(xk, Wk, bk, p_k, CC, CC, CC, CC);
    gemm_nt_bias<<<gproj, 256>>>(xv, Wv, bv_in, p_v, CC, CC, CC, CC);

    l2norm_rows<<<ROWS, 128>>>(p_q);
    l2norm_rows<<<ROWS, 128>>>(p_k);

    init_mu_b<<<BB, 256>>>(mask, p_mode, p_mu, p_bv);

    dim3 gsim(NQ / BNT, MM / BMT, BB);  // (8, 8, 8)
    gemm_sim<<<gsim, 256>>>(p_k, p_q, mask, p_mode, p_sim, p_E);

    const float nu_eff = 1.0f / (float)NQ + 1e-8f;
    for (int it = 0; it < 100; it++) {
        sk_fused<<<dim3(SK_CHUNKS, BB), 256>>>(p_E, p_bv, p_mu, mask, p_mode, p_a, p_part);
        sk_breduce<<<ROWS / 256, 256>>>(p_part, p_bv, nu_eff);
    }

    if (out_size >= NQ * BB * CC + BB * MM) {
        finalize_T_attn<<<ROWS, 256>>>(p_E, p_sim, p_a, p_bv, out + NQ * BB * CC);
    } else {
        finalize_T_attn<<<ROWS, 256>>>(p_E, p_sim, p_a, p_bv, p_a /*unused sink*/);
    }

    dim3 gx(CC / BNT, NQ / BMT, BB);    // (5, 8, 8)
    gemm_tn_x<<<gx, 256>>>(p_E, p_v, p_x);

    gemm_nt_bias<<<gproj, 256>>>(p_x, Wp, bp, out, CC, CC, CC, CC);
}